// round 15
// baseline (speedup 1.0000x reference)
#include <cuda_runtime.h>
#include <cuda_fp16.h>
#include <cstdint>
#include <cstddef>

#define TOKENS 8192
#define DIN    4096
#define DOUT   16384

// ---------------- device scratch (static: no runtime allocation) ----------------
// Packed fp16 layouts: 128row x 64col blocks (16 KB, 128B rows), SW128-swizzled.
// g_Xh: block(mt, kt) at ((mt*64 + kt) * 16384)   [mt: 64, kt: 64]   64 MB
// g_Wh: block(nt, kt) at ((nt*64 + kt) * 16384)   [nt: 128, kt: 64] 128 MB
static __device__ uint8_t g_Xh[(size_t)TOKENS * DIN * 2];
static __device__ uint8_t g_Wh[(size_t)DOUT   * DIN * 2];

// ---------------- PTX helpers ----------------
__device__ __forceinline__ uint32_t smem_u32(const void* p) {
    uint32_t a;
    asm("{ .reg .u64 t; cvta.to.shared.u64 t, %1; cvt.u32.u64 %0, t; }" : "=r"(a) : "l"(p));
    return a;
}
__device__ __forceinline__ void bulk_cp(uint32_t dst, const void* src, uint32_t bytes,
                                        uint32_t mbar) {
    asm volatile(
        "cp.async.bulk.shared::cluster.global.mbarrier::complete_tx::bytes [%0], [%1], %2, [%3];"
        :: "r"(dst), "l"(src), "r"(bytes), "r"(mbar) : "memory");
}
__device__ __forceinline__ void expect_tx(uint32_t mbar, uint32_t bytes) {
    asm volatile("mbarrier.arrive.expect_tx.shared.b64 _, [%0], %1;"
                 :: "r"(mbar), "r"(bytes) : "memory");
}
__device__ __forceinline__ void mbar_arrive(uint32_t mbar) {
    asm volatile("mbarrier.arrive.release.cta.shared.b64 _, [%0];" :: "r"(mbar) : "memory");
}
__device__ __forceinline__ void mbar_init(uint32_t addr, uint32_t cnt) {
    asm volatile("mbarrier.init.shared.b64 [%0], %1;" :: "r"(addr), "r"(cnt) : "memory");
}
__device__ __forceinline__ void mbar_wait(uint32_t addr, uint32_t parity) {
    asm volatile(
        "{\n\t.reg .pred P;\n\t"
        "LAB_WAIT_%=:\n\t"
        "mbarrier.try_wait.parity.acquire.cta.shared::cta.b64 P, [%0], %1, 0x989680;\n\t"
        "@P bra.uni LAB_DONE_%=;\n\t"
        "bra.uni LAB_WAIT_%=;\n\t"
        "LAB_DONE_%=:\n\t}"
        :: "r"(addr), "r"(parity) : "memory");
}
__device__ __forceinline__ void fence_async_to_generic() {
    // async-proxy writes (cp.async.bulk) -> generic-proxy reads (ldmatrix)
    asm volatile("fence.proxy.async.shared::cta;" ::: "memory");
}
__device__ __forceinline__ void ldsm4(uint32_t& r0, uint32_t& r1, uint32_t& r2, uint32_t& r3,
                                      uint32_t addr) {
    asm volatile("ldmatrix.sync.aligned.m8n8.x4.shared.b16 {%0,%1,%2,%3}, [%4];"
                 : "=r"(r0), "=r"(r1), "=r"(r2), "=r"(r3) : "r"(addr));
}
__device__ __forceinline__ void hmma16816(float* d, const uint32_t* a, const uint32_t* b) {
    asm volatile(
        "mma.sync.aligned.m16n8k16.row.col.f32.f16.f16.f32 "
        "{%0,%1,%2,%3}, {%4,%5,%6,%7}, {%8,%9}, {%0,%1,%2,%3};"
        : "+f"(d[0]), "+f"(d[1]), "+f"(d[2]), "+f"(d[3])
        : "r"(a[0]), "r"(a[1]), "r"(a[2]), "r"(a[3]), "r"(b[0]), "r"(b[1]));
}

// ---------------- convert kernels (write packed + swizzled fp16) ----------------
__global__ void __launch_bounds__(256) convert_w_kernel(const int* __restrict__ q) {
    size_t i = (size_t)blockIdx.x * 256 + threadIdx.x;   // int4 index (4 ints)
    int4 v = ((const int4*)q)[i];
    const int n  = (int)(i >> 10);            // DIN/4 = 1024 int4 per row
    const int k  = ((int)i & 1023) * 4;
    const int nt = n >> 7, r = n & 127, kt = k >> 6, c = k & 63;
    const size_t blk = ((size_t)nt * 64 + kt) * 16384;
    const uint32_t off = (uint32_t)(r * 128 + ((2 * c) ^ ((r & 7) << 4)));
    __half2 h0 = __halves2half2(__int2half_rn(v.x), __int2half_rn(v.y));
    __half2 h1 = __halves2half2(__int2half_rn(v.z), __int2half_rn(v.w));
    uint2 o;
    o.x = *(uint32_t*)&h0;
    o.y = *(uint32_t*)&h1;
    *(uint2*)(g_Wh + blk + off) = o;
}

__global__ void __launch_bounds__(256) convert_x_kernel(const float* __restrict__ x) {
    size_t i = (size_t)blockIdx.x * 256 + threadIdx.x;   // float4 index
    float4 v = ((const float4*)x)[i];
    const int t  = (int)(i >> 10);
    const int k  = ((int)i & 1023) * 4;
    const int mt = t >> 7, r = t & 127, kt = k >> 6, c = k & 63;
    const size_t blk = ((size_t)mt * 64 + kt) * 16384;
    const uint32_t off = (uint32_t)(r * 128 + ((2 * c) ^ ((r & 7) << 4)));
    __half2 h0 = __floats2half2_rn(v.x, v.y);
    __half2 h1 = __floats2half2_rn(v.z, v.w);
    uint2 o;
    o.x = *(uint32_t*)&h0;
    o.y = *(uint32_t*)&h1;
    *(uint2*)(g_Xh + blk + off) = o;
}

// ---------------- GEMM ----------------
// fp16 GEMM, fp32 accum. CTA tile 128(M) x 128(N), K-tile 64, 64 iters.
// 256 threads = 8 warps (2 row-bands of 64 x 4 col-bands of 32), warp tile 64x32.
// TWO CTAs per SM (launch_bounds(256,2)), 3-stage TMA pipeline, post-consume refill.
// NEW: fence.proxy.async.shared::cta after each full-wait — orders async-proxy
// TMA writes before generic-proxy ldmatrix reads (suspected R13/R14 rel_err
// drift: consumer reading a just-completed fill before write visibility).
static constexpr int STAGE_BYTES = 32768;
static constexpr int STAGES      = 3;
static constexpr int FULL_OFF    = STAGES * STAGE_BYTES;       // 98304
static constexpr int EMPTY_OFF   = FULL_OFF + STAGES * 8;      // 98328
static constexpr int SMEM_BYTES  = EMPTY_OFF + STAGES * 8;     // 98352
static constexpr int KTILES      = DIN / 64;                   // 64

__global__ void __launch_bounds__(256, 2)
qlinear_gemm(const int* __restrict__ q_bias, const float* __restrict__ scale,
             const float* __restrict__ bias_scale, float* __restrict__ out,
             int m_base)
{
    extern __shared__ char smem[];
    const uint32_t sb = smem_u32(smem);
    const int tid  = threadIdx.x;
    const int wid  = tid >> 5;
    const int lane = tid & 31;
    const int wrow = wid >> 2;            // 0..1 : rows 64*wrow..+63 (of 128)
    const int wcol = wid & 3;             // 0..3 : cols 32*wcol..+31

    // launch covers 16 m-tiles x 128 n-tiles = 2048 CTAs; m fastest so 16
    // consecutive CTAs share one W n-slice and the launch A chunk stays in L2.
    const int bid    = blockIdx.x;
    const int m_tile = (m_base >> 7) + (bid & 15);
    const int n_tile = bid >> 4;
    const int m0     = m_tile * 128;
    const int n0     = n_tile * 128;

    if (tid == 0) {
#pragma unroll
        for (int s = 0; s < STAGES; ++s) {
            mbar_init(sb + FULL_OFF + s * 8, 1);     // tx-based
            mbar_init(sb + EMPTY_OFF + s * 8, 8);    // one lane per warp
        }
    }
    __syncthreads();

    const uint8_t* a_src = g_Xh + ((size_t)m_tile * 64) * 16384;
    const uint8_t* w_src = g_Wh + ((size_t)n_tile * 64) * 16384;

    // prologue: fill ALL 3 stages (k-tiles 0,1,2)
    if (tid == 0) {
#pragma unroll
        for (int s = 0; s < STAGES; ++s) {
            const uint32_t mb  = sb + FULL_OFF + s * 8;
            const uint32_t dst = sb + s * STAGE_BYTES;
            expect_tx(mb, STAGE_BYTES);
            bulk_cp(dst,         a_src + (size_t)s * 16384, 16384, mb);
            bulk_cp(dst + 16384, w_src + (size_t)s * 16384, 16384, mb);
        }
    }

    // per-lane operand addressing (swizzle folded into k-byte XOR)
    const int arow = wrow * 64 + (lane & 15);
    const uint32_t aBase = (uint32_t)arow * 128;
    const uint32_t axor  = (uint32_t)((arow & 7) << 4);
    const int brow = wcol * 32 + ((lane >> 4) << 3) + (lane & 7);
    const uint32_t bBase = 16384u + (uint32_t)brow * 128;      // second ldsm +2048
    const uint32_t bxor  = (uint32_t)((brow & 7) << 4);
    uint32_t aoff[4], boff[4];
#pragma unroll
    for (int ks = 0; ks < 4; ++ks) {
        aoff[ks] = ((uint32_t)(ks * 32) + (uint32_t)((lane >> 4) * 16)) ^ axor;
        boff[ks] = ((uint32_t)(ks * 32) + (uint32_t)(((lane >> 3) & 1) * 16)) ^ bxor;
    }

    float acc[4][4][4] = {};
    int cbuf = 0, cph = 0;          // consumer stage / fill-parity (flips on wrap)

#pragma unroll 1
    for (int i = 0; i < KTILES; ++i) {
        mbar_wait(sb + FULL_OFF + cbuf * 8, cph);
        fence_async_to_generic();             // TMA writes -> ldsm reads visibility

        const uint32_t stg = sb + (uint32_t)cbuf * STAGE_BYTES;
#pragma unroll
        for (int ks = 0; ks < 4; ++ks) {
            uint32_t b[4][2];
            // sequential pairing (proven): first ldsm = band rows 0-15
            ldsm4(b[0][0], b[0][1], b[1][0], b[1][1], stg + bBase + boff[ks]);
            ldsm4(b[2][0], b[2][1], b[3][0], b[3][1], stg + bBase + 2048 + boff[ks]);
#pragma unroll
            for (int mt = 0; mt < 4; ++mt) {
                uint32_t a[4];
                ldsm4(a[0], a[1], a[2], a[3], stg + aBase + mt * 2048 + aoff[ks]);
                hmma16816(acc[mt][0], a, b[0]);
                hmma16816(acc[mt][1], a, b[1]);
                hmma16816(acc[mt][2], a, b[2]);
                hmma16816(acc[mt][3], a, b[3]);
            }
        }
        // release: ldsm data is in registers before the HMMAs (and thus this
        // arrive) can issue -> lane-0 arrive after syncwarp is sufficient.
        __syncwarp();
        if (lane == 0) mbar_arrive(sb + EMPTY_OFF + cbuf * 8);

        // post-consume refill: thread 0 reloads THIS buffer with k-tile i+3
        if (tid == 0 && i + 3 < KTILES) {
            mbar_wait(sb + EMPTY_OFF + cbuf * 8, (i / 3) & 1);   // all 8 warps done
            const uint32_t mb  = sb + FULL_OFF + cbuf * 8;
            expect_tx(mb, STAGE_BYTES);
            bulk_cp(stg,         a_src + (size_t)(i + 3) * 16384, 16384, mb);
            bulk_cp(stg + 16384, w_src + (size_t)(i + 3) * 16384, 16384, mb);
        }
        if (++cbuf == STAGES) { cbuf = 0; cph ^= 1; }
    }

    // ---------------- epilogue: out = sc*acc + bias, direct stores ----------------
    const float sc  = scale[0];
    const float bsc = bias_scale[0];
    const int r  = lane >> 2;             // 0..7
    const int kg = lane & 3;              // 0..3

#pragma unroll
    for (int nt = 0; nt < 4; ++nt) {
        const int col = wcol * 32 + nt * 8 + kg * 2;
        const int2 qb = *(const int2*)(q_bias + n0 + col);
        const float b0 = qb.x * bsc, b1 = qb.y * bsc;
#pragma unroll
        for (int mt = 0; mt < 4; ++mt) {
            const int row = wrow * 64 + mt * 16 + r;
            float2 r0, r1;
            r0.x = sc * acc[mt][nt][0] + b0;
            r0.y = sc * acc[mt][nt][1] + b1;
            r1.x = sc * acc[mt][nt][2] + b0;
            r1.y = sc * acc[mt][nt][3] + b1;
            *(float2*)(out + (size_t)(m0 + row)     * DOUT + n0 + col) = r0;
            *(float2*)(out + (size_t)(m0 + row + 8) * DOUT + n0 + col) = r1;
        }
    }
}

// ---------------- launch ----------------
extern "C" void kernel_launch(void* const* d_in, const int* in_sizes, int n_in,
                              void* d_out, int out_size) {
    const float* x   = (const float*)d_in[0];
    const int*   qw  = (const int*)d_in[1];
    const int*   qb  = (const int*)d_in[2];
    const float* sc  = (const float*)d_in[3];
    const float* bsc = (const float*)d_in[4];
    float* out = (float*)d_out;

    cudaFuncSetAttribute(qlinear_gemm, cudaFuncAttributeMaxDynamicSharedMemorySize, SMEM_BYTES);

    convert_w_kernel<<<(DOUT * (size_t)DIN) / 4 / 256, 256>>>(qw);   // 65536 blocks
    convert_x_kernel<<<(TOKENS * (size_t)DIN) / 4 / 256, 256>>>(x);  // 32768 blocks
    // GEMM split into 4 M-chunks (2048 tokens each) so ncu (-s 5 -c 1) lands on it.
    for (int c = 0; c < 4; ++c)
        qlinear_gemm<<<16 * 128, 256, SMEM_BYTES>>>(qb, sc, bsc, out, c * 2048);
}

// round 16
// speedup vs baseline: 1.0466x; 1.0466x over previous
#include <cuda_runtime.h>
#include <cuda_fp16.h>
#include <cstdint>
#include <cstddef>

#define TOKENS 8192
#define DIN    4096
#define DOUT   16384

// ---------------- device scratch (static: no runtime allocation) ----------------
// Packed fp16 layouts: 128row x 64col blocks (16 KB, 128B rows), SW128-swizzled.
// g_Xh: block(mt, kt) at ((mt*64 + kt) * 16384)   [mt: 64, kt: 64]   64 MB
// g_Wh: block(nt, kt) at ((nt*64 + kt) * 16384)   [nt: 128, kt: 64] 128 MB
static __device__ uint8_t g_Xh[(size_t)TOKENS * DIN * 2];
static __device__ uint8_t g_Wh[(size_t)DOUT   * DIN * 2];

// ---------------- PTX helpers ----------------
__device__ __forceinline__ uint32_t smem_u32(const void* p) {
    uint32_t a;
    asm("{ .reg .u64 t; cvta.to.shared.u64 t, %1; cvt.u32.u64 %0, t; }" : "=r"(a) : "l"(p));
    return a;
}
__device__ __forceinline__ void bulk_cp(uint32_t dst, const void* src, uint32_t bytes,
                                        uint32_t mbar) {
    asm volatile(
        "cp.async.bulk.shared::cluster.global.mbarrier::complete_tx::bytes [%0], [%1], %2, [%3];"
        :: "r"(dst), "l"(src), "r"(bytes), "r"(mbar) : "memory");
}
__device__ __forceinline__ void expect_tx(uint32_t mbar, uint32_t bytes) {
    asm volatile("mbarrier.arrive.expect_tx.shared.b64 _, [%0], %1;"
                 :: "r"(mbar), "r"(bytes) : "memory");
}
__device__ __forceinline__ void mbar_arrive(uint32_t mbar) {
    asm volatile("mbarrier.arrive.release.cta.shared.b64 _, [%0];" :: "r"(mbar) : "memory");
}
__device__ __forceinline__ void mbar_init(uint32_t addr, uint32_t cnt) {
    asm volatile("mbarrier.init.shared.b64 [%0], %1;" :: "r"(addr), "r"(cnt) : "memory");
}
__device__ __forceinline__ void mbar_wait(uint32_t addr, uint32_t parity) {
    asm volatile(
        "{\n\t.reg .pred P;\n\t"
        "LAB_WAIT_%=:\n\t"
        "mbarrier.try_wait.parity.acquire.cta.shared::cta.b64 P, [%0], %1, 0x989680;\n\t"
        "@P bra.uni LAB_DONE_%=;\n\t"
        "bra.uni LAB_WAIT_%=;\n\t"
        "LAB_DONE_%=:\n\t}"
        :: "r"(addr), "r"(parity) : "memory");
}
__device__ __forceinline__ void fence_async_to_generic() {
    asm volatile("fence.proxy.async.shared::cta;" ::: "memory");
}
__device__ __forceinline__ void ldsm4(uint32_t& r0, uint32_t& r1, uint32_t& r2, uint32_t& r3,
                                      uint32_t addr) {
    asm volatile("ldmatrix.sync.aligned.m8n8.x4.shared.b16 {%0,%1,%2,%3}, [%4];"
                 : "=r"(r0), "=r"(r1), "=r"(r2), "=r"(r3) : "r"(addr));
}
__device__ __forceinline__ void hmma16816(float* d, const uint32_t* a, const uint32_t* b) {
    asm volatile(
        "mma.sync.aligned.m16n8k16.row.col.f32.f16.f16.f32 "
        "{%0,%1,%2,%3}, {%4,%5,%6,%7}, {%8,%9}, {%0,%1,%2,%3};"
        : "+f"(d[0]), "+f"(d[1]), "+f"(d[2]), "+f"(d[3])
        : "r"(a[0]), "r"(a[1]), "r"(a[2]), "r"(a[3]), "r"(b[0]), "r"(b[1]));
}

// ---------------- convert kernels (write packed + swizzled fp16) ----------------
__global__ void __launch_bounds__(256) convert_w_kernel(const int* __restrict__ q) {
    size_t i = (size_t)blockIdx.x * 256 + threadIdx.x;   // int4 index (4 ints)
    int4 v = ((const int4*)q)[i];
    const int n  = (int)(i >> 10);            // DIN/4 = 1024 int4 per row
    const int k  = ((int)i & 1023) * 4;
    const int nt = n >> 7, r = n & 127, kt = k >> 6, c = k & 63;
    const size_t blk = ((size_t)nt * 64 + kt) * 16384;
    const uint32_t off = (uint32_t)(r * 128 + ((2 * c) ^ ((r & 7) << 4)));
    __half2 h0 = __halves2half2(__int2half_rn(v.x), __int2half_rn(v.y));
    __half2 h1 = __halves2half2(__int2half_rn(v.z), __int2half_rn(v.w));
    uint2 o;
    o.x = *(uint32_t*)&h0;
    o.y = *(uint32_t*)&h1;
    *(uint2*)(g_Wh + blk + off) = o;
}

__global__ void __launch_bounds__(256) convert_x_kernel(const float* __restrict__ x) {
    size_t i = (size_t)blockIdx.x * 256 + threadIdx.x;   // float4 index
    float4 v = ((const float4*)x)[i];
    const int t  = (int)(i >> 10);
    const int k  = ((int)i & 1023) * 4;
    const int mt = t >> 7, r = t & 127, kt = k >> 6, c = k & 63;
    const size_t blk = ((size_t)mt * 64 + kt) * 16384;
    const uint32_t off = (uint32_t)(r * 128 + ((2 * c) ^ ((r & 7) << 4)));
    __half2 h0 = __floats2half2_rn(v.x, v.y);
    __half2 h1 = __floats2half2_rn(v.z, v.w);
    uint2 o;
    o.x = *(uint32_t*)&h0;
    o.y = *(uint32_t*)&h1;
    *(uint2*)(g_Xh + blk + off) = o;
}

// ---------------- GEMM ----------------
// fp16 GEMM, fp32 accum. CTA tile 128(M) x 128(N), K-tile 64, 64 iters.
// 256 threads = 8 warps (2 row-bands of 64 x 4 col-bands of 32), warp tile 64x32.
// TWO CTAs per SM, 3-stage TMA pipeline, post-consume refill, proxy fence.
// SINGLE fused launch (8192 CTAs) in 2048-CTA chunks: same raster/L2 behavior
// as the 4-launch version, minus 3 launch gaps + 3 partial-wave tails.
static constexpr int STAGE_BYTES = 32768;
static constexpr int STAGES      = 3;
static constexpr int FULL_OFF    = STAGES * STAGE_BYTES;       // 98304
static constexpr int EMPTY_OFF   = FULL_OFF + STAGES * 8;      // 98328
static constexpr int SMEM_BYTES  = EMPTY_OFF + STAGES * 8;     // 98352
static constexpr int KTILES      = DIN / 64;                   // 64

__global__ void __launch_bounds__(256, 2)
qlinear_gemm(const int* __restrict__ q_bias, const float* __restrict__ scale,
             const float* __restrict__ bias_scale, float* __restrict__ out)
{
    extern __shared__ char smem[];
    const uint32_t sb = smem_u32(smem);
    const int tid  = threadIdx.x;
    const int wid  = tid >> 5;
    const int lane = tid & 31;
    const int wrow = wid >> 2;            // 0..1 : rows 64*wrow..+63 (of 128)
    const int wcol = wid & 3;             // 0..3 : cols 32*wcol..+31

    // fused raster: 2048-CTA chunks; within a chunk m fastest (16 m-tiles
    // share one W n-slice; chunk A footprint 16MB stays L2-resident).
    const int bid    = blockIdx.x;
    const int chunk  = bid >> 11;                 // 0..3
    const int m_tile = (chunk << 4) + (bid & 15); // 0..63
    const int n_tile = (bid >> 4) & 127;
    const int m0     = m_tile * 128;
    const int n0     = n_tile * 128;

    if (tid == 0) {
#pragma unroll
        for (int s = 0; s < STAGES; ++s) {
            mbar_init(sb + FULL_OFF + s * 8, 1);     // tx-based
            mbar_init(sb + EMPTY_OFF + s * 8, 8);    // one lane per warp
        }
    }
    __syncthreads();

    const uint8_t* a_src = g_Xh + ((size_t)m_tile * 64) * 16384;
    const uint8_t* w_src = g_Wh + ((size_t)n_tile * 64) * 16384;

    // prologue: fill ALL 3 stages (k-tiles 0,1,2)
    if (tid == 0) {
#pragma unroll
        for (int s = 0; s < STAGES; ++s) {
            const uint32_t mb  = sb + FULL_OFF + s * 8;
            const uint32_t dst = sb + s * STAGE_BYTES;
            expect_tx(mb, STAGE_BYTES);
            bulk_cp(dst,         a_src + (size_t)s * 16384, 16384, mb);
            bulk_cp(dst + 16384, w_src + (size_t)s * 16384, 16384, mb);
        }
    }

    // per-lane operand addressing (swizzle folded into k-byte XOR)
    const int arow = wrow * 64 + (lane & 15);
    const uint32_t aBase = (uint32_t)arow * 128;
    const uint32_t axor  = (uint32_t)((arow & 7) << 4);
    const int brow = wcol * 32 + ((lane >> 4) << 3) + (lane & 7);
    const uint32_t bBase = 16384u + (uint32_t)brow * 128;      // second ldsm +2048
    const uint32_t bxor  = (uint32_t)((brow & 7) << 4);
    uint32_t aoff[4], boff[4];
#pragma unroll
    for (int ks = 0; ks < 4; ++ks) {
        aoff[ks] = ((uint32_t)(ks * 32) + (uint32_t)((lane >> 4) * 16)) ^ axor;
        boff[ks] = ((uint32_t)(ks * 32) + (uint32_t)(((lane >> 3) & 1) * 16)) ^ bxor;
    }

    float acc[4][4][4] = {};
    int cbuf = 0, cph = 0;          // consumer stage / fill-parity (flips on wrap)

#pragma unroll 1
    for (int i = 0; i < KTILES; ++i) {
        mbar_wait(sb + FULL_OFF + cbuf * 8, cph);
        fence_async_to_generic();             // TMA writes -> ldsm reads visibility

        const uint32_t stg = sb + (uint32_t)cbuf * STAGE_BYTES;
#pragma unroll
        for (int ks = 0; ks < 4; ++ks) {
            uint32_t b[4][2];
            // sequential pairing (proven): first ldsm = band rows 0-15
            ldsm4(b[0][0], b[0][1], b[1][0], b[1][1], stg + bBase + boff[ks]);
            ldsm4(b[2][0], b[2][1], b[3][0], b[3][1], stg + bBase + 2048 + boff[ks]);
#pragma unroll
            for (int mt = 0; mt < 4; ++mt) {
                uint32_t a[4];
                ldsm4(a[0], a[1], a[2], a[3], stg + aBase + mt * 2048 + aoff[ks]);
                hmma16816(acc[mt][0], a, b[0]);
                hmma16816(acc[mt][1], a, b[1]);
                hmma16816(acc[mt][2], a, b[2]);
                hmma16816(acc[mt][3], a, b[3]);
            }
        }
        // release: ldsm data is register-resident before the HMMAs (and thus
        // this arrive) can issue -> lane-0 arrive after syncwarp is sufficient.
        __syncwarp();
        if (lane == 0) mbar_arrive(sb + EMPTY_OFF + cbuf * 8);

        // post-consume refill: thread 0 reloads THIS buffer with k-tile i+3
        if (tid == 0 && i + 3 < KTILES) {
            mbar_wait(sb + EMPTY_OFF + cbuf * 8, (i / 3) & 1);   // all 8 warps done
            const uint32_t mb  = sb + FULL_OFF + cbuf * 8;
            expect_tx(mb, STAGE_BYTES);
            bulk_cp(stg,         a_src + (size_t)(i + 3) * 16384, 16384, mb);
            bulk_cp(stg + 16384, w_src + (size_t)(i + 3) * 16384, 16384, mb);
        }
        if (++cbuf == STAGES) { cbuf = 0; cph ^= 1; }
    }

    // ---------------- epilogue: out = sc*acc + bias, direct stores ----------------
    const float sc  = scale[0];
    const float bsc = bias_scale[0];
    const int r  = lane >> 2;             // 0..7
    const int kg = lane & 3;              // 0..3

#pragma unroll
    for (int nt = 0; nt < 4; ++nt) {
        const int col = wcol * 32 + nt * 8 + kg * 2;
        const int2 qb = *(const int2*)(q_bias + n0 + col);
        const float b0 = qb.x * bsc, b1 = qb.y * bsc;
#pragma unroll
        for (int mt = 0; mt < 4; ++mt) {
            const int row = wrow * 64 + mt * 16 + r;
            float2 r0, r1;
            r0.x = sc * acc[mt][nt][0] + b0;
            r0.y = sc * acc[mt][nt][1] + b1;
            r1.x = sc * acc[mt][nt][2] + b0;
            r1.y = sc * acc[mt][nt][3] + b1;
            *(float2*)(out + (size_t)(m0 + row)     * DOUT + n0 + col) = r0;
            *(float2*)(out + (size_t)(m0 + row + 8) * DOUT + n0 + col) = r1;
        }
    }
}

// ---------------- launch ----------------
extern "C" void kernel_launch(void* const* d_in, const int* in_sizes, int n_in,
                              void* d_out, int out_size) {
    const float* x   = (const float*)d_in[0];
    const int*   qw  = (const int*)d_in[1];
    const int*   qb  = (const int*)d_in[2];
    const float* sc  = (const float*)d_in[3];
    const float* bsc = (const float*)d_in[4];
    float* out = (float*)d_out;

    cudaFuncSetAttribute(qlinear_gemm, cudaFuncAttributeMaxDynamicSharedMemorySize, SMEM_BYTES);

    convert_w_kernel<<<(DOUT * (size_t)DIN) / 4 / 256, 256>>>(qw);   // 65536 blocks
    convert_x_kernel<<<(TOKENS * (size_t)DIN) / 4 / 256, 256>>>(x);  // 32768 blocks
    qlinear_gemm<<<64 * 128, 256, SMEM_BYTES>>>(qb, sc, bsc, out);   // single fused launch
}